// round 2
// baseline (speedup 1.0000x reference)
#include <cuda_runtime.h>
#include <math.h>

#define NT 65536
#define DD 256
#define NE 16
#define HH 256
#define OO 256
#define GH 1024

#define BM 128
#define BN 128
#define BKK 16

typedef unsigned long long u64;

// ---------------- scratch (static device globals; no allocation) ----------------
__device__ float g_h1[(size_t)NT * GH];          // 256 MB: gate hidden 1
__device__ float g_h2[(size_t)NT * DD];          // 64 MB : gate hidden 2
__device__ int   g_top_i[NT * 2];
__device__ float g_top_w[NT * 2];
__device__ int   g_counts[NE];
__device__ int   g_offsets[NE];
__device__ int   g_base[NE + 1];
__device__ int   g_perm_tok[NT * 2];
__device__ float g_perm_w[NT * 2];
__device__ float g_he[(size_t)(NT * 2) * HH];    // 134 MB: expert hidden

// ---------------- packed f32x2 helpers (sm_100+) ----------------
__device__ __forceinline__ void fma2(u64 &d, u64 a, u64 b) {
    asm("fma.rn.f32x2 %0, %1, %2, %0;" : "+l"(d) : "l"(a), "l"(b));
}
__device__ __forceinline__ u64 dup2(float v) {
    union { float2 f; u64 u; } cv; cv.f = make_float2(v, v); return cv.u;
}
__device__ __forceinline__ float2 unpk(u64 v) {
    union { u64 u; float2 f; } cv; cv.u = v; return cv.f;
}

// ---------------- small bookkeeping kernels ----------------
__global__ void init_kernel() {
    if (threadIdx.x < NE) g_counts[threadIdx.x] = 0;
}

__global__ void prefix_kernel() {
    if (threadIdx.x == 0) {
        int s = 0;
        for (int e = 0; e < NE; e++) {
            g_base[e] = s;
            s += g_counts[e];
            g_offsets[e] = 0;
        }
        g_base[NE] = s;
    }
}

__global__ void scatter_kernel() {
    int b = blockIdx.x * blockDim.x + threadIdx.x;
    if (b >= NT) return;
#pragma unroll
    for (int s = 0; s < 2; s++) {
        int e = g_top_i[b * 2 + s];
        int pos = atomicAdd(&g_offsets[e], 1);
        int idx = g_base[e] + pos;
        g_perm_tok[idx] = b;
        g_perm_w[idx] = g_top_w[b * 2 + s];
    }
}

// ---------------- gate layer 3 + softmax + top-2 + renorm ----------------
// one warp per token; 8 tokens per 256-thread block
__global__ void gate3_kernel(const float* __restrict__ h2,
                             const float* __restrict__ g3,
                             const float* __restrict__ gb3,
                             float* __restrict__ y_out,
                             float* __restrict__ p_out) {
    __shared__ float s_g3t[NE][DD];   // transposed: [e][k], conflict-free reads
    int tid = threadIdx.x;
    for (int i = tid; i < DD * NE; i += 256) {
        int k = i >> 4, e = i & 15;
        s_g3t[e][k] = g3[i];
    }
    __syncthreads();

    int warp = tid >> 5, lane = tid & 31;
    int b = blockIdx.x * 8 + warp;

    float acc[NE];
#pragma unroll
    for (int e = 0; e < NE; e++) acc[e] = 0.f;

    const float* hrow = h2 + (size_t)b * DD;
#pragma unroll
    for (int j = 0; j < DD / 32; j++) {
        int k = lane + j * 32;
        float hv = hrow[k];
#pragma unroll
        for (int e = 0; e < NE; e++) acc[e] = fmaf(hv, s_g3t[e][k], acc[e]);
    }
#pragma unroll
    for (int e = 0; e < NE; e++) {
#pragma unroll
        for (int off = 16; off; off >>= 1)
            acc[e] += __shfl_xor_sync(0xffffffffu, acc[e], off);
        acc[e] += gb3[e];    // logits now in every lane
    }

    // softmax + top-2 (computed redundantly in every lane; cheap)
    float m = acc[0];
#pragma unroll
    for (int e = 1; e < NE; e++) m = fmaxf(m, acc[e]);
    float pe[NE];
    float Z = 0.f;
#pragma unroll
    for (int e = 0; e < NE; e++) { pe[e] = expf(acc[e] - m); Z += pe[e]; }
    float invZ = 1.f / Z;

    int i1 = 0; float v1 = pe[0];
#pragma unroll
    for (int e = 1; e < NE; e++) if (pe[e] > v1) { v1 = pe[e]; i1 = e; }
    int i2 = -1; float v2 = -1.f;
#pragma unroll
    for (int e = 0; e < NE; e++) if (e != i1 && pe[e] > v2) { v2 = pe[e]; i2 = e; }

    float t1 = v1 * invZ, t2 = v2 * invZ;
    float denom = t1 + t2 + 1e-9f;
    float w1 = t1 / denom, w2 = t2 / denom;

    // write p row (16 floats)
    if (lane < NE)
        p_out[(size_t)b * NE + lane] = (lane == i1) ? w1 : ((lane == i2) ? w2 : 0.f);
    // zero y row (accumulated later by expert stage 2)
#pragma unroll
    for (int j = 0; j < OO / 32; j++)
        y_out[(size_t)b * OO + lane + j * 32] = 0.f;

    if (lane == 0) {
        g_top_i[b * 2 + 0] = i1;
        g_top_i[b * 2 + 1] = i2;
        g_top_w[b * 2 + 0] = w1;
        g_top_w[b * 2 + 1] = w2;
        atomicAdd(&g_counts[i1], 1);
        atomicAdd(&g_counts[i2], 1);
    }
}

// ---------------- tiled fp32 GEMM (f32x2 packed FMA) ----------------
// MODE 0: C[M,N] = relu(A[M,K] @ W[K,N] + preb[N])              (gate layers 1,2)
// MODE 1: he[slot,N] = relu((x[tok]+ebias[e]) @ W1_e + b1_e)    (expert stage 1, gathered)
// MODE 2: y[tok] += w_slot * ((he[slot] @ W2_e) + b2_e)         (expert stage 2, atomic)
template<int MODE>
__global__ __launch_bounds__(256, 2)
void gemm_tpl(const float* __restrict__ A,
              const float* __restrict__ W,
              const float* __restrict__ preb,
              const float* __restrict__ ebias,
              float* __restrict__ C,
              int N, int K) {
    __shared__ __align__(16) float As[BKK][BM];
    __shared__ __align__(16) float Ws[BKK][BN];
    __shared__ int   s_row[BM];
    __shared__ int   s_tok[BM];
    __shared__ float s_wgt[BM];

    int tid = threadIdx.x;
    int bm = 0, bn;
    int e = 0, rows = BM, tbase = 0;

    if (MODE == 0) {
        bm = blockIdx.x * BM;
        bn = blockIdx.y * BN;
    } else {
        e = blockIdx.z;
        int nbeg = g_base[e];
        int ne = g_base[e + 1] - nbeg;
        int t0 = blockIdx.x * BM;
        if (t0 >= ne) return;
        rows = min(BM, ne - t0);
        tbase = nbeg + t0;
        bn = blockIdx.y * BN;
        for (int mm = tid; mm < BM; mm += 256) {
            int mc = min(mm, rows - 1);
            int slot = tbase + mc;
            if (MODE == 1) {
                s_row[mm] = g_perm_tok[slot];
            } else {
                s_row[mm] = slot;
                s_tok[mm] = g_perm_tok[slot];
                s_wgt[mm] = g_perm_w[slot];
            }
        }
        __syncthreads();
    }

    const float* Wp = (MODE == 0) ? W : (W + (size_t)e * K * N);

    int tr = tid >> 4;   // 0..15 -> rows tr*8 .. tr*8+7
    int tc = tid & 15;   // 0..15 -> cols tc*8 .. tc*8+7

    u64 acc[4][8];
#pragma unroll
    for (int i = 0; i < 4; i++)
#pragma unroll
        for (int j = 0; j < 8; j++) acc[i][j] = 0ull;

    for (int k0 = 0; k0 < K; k0 += BKK) {
        // --- load A tile (transposed into As[k][m]) ---
#pragma unroll
        for (int i = 0; i < 2; i++) {
            int f = tid * 2 + i;          // 0..511
            int m = f >> 2;
            int c = (f & 3) << 2;
            float4 v;
            if (MODE == 0) {
                v = *(const float4*)&A[(size_t)(bm + m) * K + k0 + c];
            } else if (MODE == 1) {
                float4 xv = *(const float4*)&A[(size_t)s_row[m] * K + k0 + c];
                float4 bv = *(const float4*)&ebias[(size_t)e * K + k0 + c];
                v = make_float4(xv.x + bv.x, xv.y + bv.y, xv.z + bv.z, xv.w + bv.w);
            } else {
                v = *(const float4*)&A[(size_t)s_row[m] * K + k0 + c];
            }
            As[c + 0][m] = v.x;
            As[c + 1][m] = v.y;
            As[c + 2][m] = v.z;
            As[c + 3][m] = v.w;
        }
        // --- load W tile ---
#pragma unroll
        for (int i = 0; i < 2; i++) {
            int f = tid * 2 + i;
            int r = f >> 5;               // 0..15
            int c = (f & 31) << 2;        // 0..124
            *(float4*)&Ws[r][c] = *(const float4*)&Wp[(size_t)(k0 + r) * N + bn + c];
        }
        __syncthreads();

        // --- compute: 128x128 tile, rows paired in f32x2 lanes ---
#pragma unroll
        for (int k = 0; k < BKK; k++) {
            u64 a2[4];
            {
                const ulonglong2* ap = (const ulonglong2*)&As[k][tr * 8];
                ulonglong2 p0 = ap[0], p1 = ap[1];
                a2[0] = p0.x; a2[1] = p0.y; a2[2] = p1.x; a2[3] = p1.y;
            }
            float4 wv0 = *(const float4*)&Ws[k][tc * 8];
            float4 wv1 = *(const float4*)&Ws[k][tc * 8 + 4];
            u64 b2r[8] = { dup2(wv0.x), dup2(wv0.y), dup2(wv0.z), dup2(wv0.w),
                           dup2(wv1.x), dup2(wv1.y), dup2(wv1.z), dup2(wv1.w) };
#pragma unroll
            for (int i = 0; i < 4; i++)
#pragma unroll
                for (int j = 0; j < 8; j++)
                    fma2(acc[i][j], a2[i], b2r[j]);
        }
        __syncthreads();
    }

    // --- epilogue ---
    float bv[8];
    {
        const float* pb = preb + ((MODE == 0) ? 0 : (size_t)e * N) + bn + tc * 8;
#pragma unroll
        for (int j = 0; j < 8; j++) bv[j] = pb[j];
    }

#pragma unroll
    for (int i = 0; i < 4; i++) {
        float lo[8], hi[8];
#pragma unroll
        for (int j = 0; j < 8; j++) {
            float2 c2 = unpk(acc[i][j]);
            lo[j] = c2.x + bv[j];
            hi[j] = c2.y + bv[j];
        }
        int m0 = tr * 8 + 2 * i;
        if (MODE == 0) {
            float* cp0 = C + (size_t)(bm + m0) * N + bn + tc * 8;
            float* cp1 = C + (size_t)(bm + m0 + 1) * N + bn + tc * 8;
            *(float4*)cp0       = make_float4(fmaxf(lo[0],0.f), fmaxf(lo[1],0.f), fmaxf(lo[2],0.f), fmaxf(lo[3],0.f));
            *(float4*)(cp0 + 4) = make_float4(fmaxf(lo[4],0.f), fmaxf(lo[5],0.f), fmaxf(lo[6],0.f), fmaxf(lo[7],0.f));
            *(float4*)cp1       = make_float4(fmaxf(hi[0],0.f), fmaxf(hi[1],0.f), fmaxf(hi[2],0.f), fmaxf(hi[3],0.f));
            *(float4*)(cp1 + 4) = make_float4(fmaxf(hi[4],0.f), fmaxf(hi[5],0.f), fmaxf(hi[6],0.f), fmaxf(hi[7],0.f));
        } else if (MODE == 1) {
            if (m0 < rows) {
                float* cp = C + (size_t)(tbase + m0) * N + bn + tc * 8;
                *(float4*)cp       = make_float4(fmaxf(lo[0],0.f), fmaxf(lo[1],0.f), fmaxf(lo[2],0.f), fmaxf(lo[3],0.f));
                *(float4*)(cp + 4) = make_float4(fmaxf(lo[4],0.f), fmaxf(lo[5],0.f), fmaxf(lo[6],0.f), fmaxf(lo[7],0.f));
            }
            if (m0 + 1 < rows) {
                float* cp = C + (size_t)(tbase + m0 + 1) * N + bn + tc * 8;
                *(float4*)cp       = make_float4(fmaxf(hi[0],0.f), fmaxf(hi[1],0.f), fmaxf(hi[2],0.f), fmaxf(hi[3],0.f));
                *(float4*)(cp + 4) = make_float4(fmaxf(hi[4],0.f), fmaxf(hi[5],0.f), fmaxf(hi[6],0.f), fmaxf(hi[7],0.f));
            }
        } else {
            if (m0 < rows) {
                int tok = s_tok[m0]; float w = s_wgt[m0];
                float* yp = C + (size_t)tok * N + bn + tc * 8;
#pragma unroll
                for (int j = 0; j < 8; j++) atomicAdd(&yp[j], lo[j] * w);
            }
            if (m0 + 1 < rows) {
                int tok = s_tok[m0 + 1]; float w = s_wgt[m0 + 1];
                float* yp = C + (size_t)tok * N + bn + tc * 8;
#pragma unroll
                for (int j = 0; j < 8; j++) atomicAdd(&yp[j], hi[j] * w);
            }
        }
    }
}

// ---------------- launch ----------------
extern "C" void kernel_launch(void* const* d_in, const int* in_sizes, int n_in,
                              void* d_out, int out_size) {
    const float* x     = (const float*)d_in[0];
    const float* ebias = (const float*)d_in[1];
    const float* W1    = (const float*)d_in[2];
    const float* b1    = (const float*)d_in[3];
    const float* W2    = (const float*)d_in[4];
    const float* b2    = (const float*)d_in[5];
    const float* g1    = (const float*)d_in[6];
    const float* gb1   = (const float*)d_in[7];
    const float* g2    = (const float*)d_in[8];
    const float* gb2   = (const float*)d_in[9];
    const float* g3    = (const float*)d_in[10];
    const float* gb3   = (const float*)d_in[11];

    float* y = (float*)d_out;                       // [NT, OO]
    float* p = y + (size_t)NT * OO;                 // [NT, NE]

    float *h1p, *h2p, *hep;
    cudaGetSymbolAddress((void**)&h1p, g_h1);
    cudaGetSymbolAddress((void**)&h2p, g_h2);
    cudaGetSymbolAddress((void**)&hep, g_he);

    init_kernel<<<1, 32>>>();

    // gate layer 1: h1 = relu(x @ g1 + gb1)   [65536,256]x[256,1024]
    gemm_tpl<0><<<dim3(NT / BM, GH / BN), 256>>>(x, g1, gb1, nullptr, h1p, GH, DD);
    // gate layer 2: h2 = relu(h1 @ g2 + gb2)  [65536,1024]x[1024,256]
    gemm_tpl<0><<<dim3(NT / BM, DD / BN), 256>>>(h1p, g2, gb2, nullptr, h2p, DD, GH);
    // gate layer 3 + softmax + top2 + renorm; also zeroes y
    gate3_kernel<<<NT / 8, 256>>>(h2p, g3, gb3, y, p);

    prefix_kernel<<<1, 32>>>();
    scatter_kernel<<<NT / 256, 256>>>();

    // expert stage 1: he = relu((x+bias_e) @ W1_e + b1_e), grouped by expert
    gemm_tpl<1><<<dim3(NT * 2 / BM, HH / BN, NE), 256>>>(x, W1, b1, ebias, hep, HH, DD);
    // expert stage 2: y[tok] += w * (he @ W2_e + b2_e)
    gemm_tpl<2><<<dim3(NT * 2 / BM, OO / BN, NE), 256>>>(hep, W2, b2, nullptr, y, OO, HH);
}

// round 5
// speedup vs baseline: 1.0001x; 1.0001x over previous
#include <cuda_runtime.h>
#include <math.h>

#define NT 65536
#define DD 256
#define NE 16
#define HH 256
#define OO 256
#define GH 1024

#define BM 128
#define BN 128
#define BKK 16

typedef unsigned long long u64;

// ---------------- scratch (static device globals; no allocation) ----------------
__device__ float g_h1[(size_t)NT * GH];          // 256 MB: gate hidden 1
__device__ float g_h2[(size_t)NT * DD];          // 64 MB : gate hidden 2
__device__ int   g_top_i[NT * 2];
__device__ float g_top_w[NT * 2];
__device__ int   g_counts[NE];
__device__ int   g_offsets[NE];
__device__ int   g_base[NE + 1];
__device__ int   g_perm_tok[NT * 2];
__device__ float g_perm_w[NT * 2];
__device__ float g_he[(size_t)(NT * 2) * HH];    // 134 MB: expert hidden

// ---------------- packed f32x2 helpers (sm_100+) ----------------
__device__ __forceinline__ void fma2(u64 &d, u64 a, u64 b) {
    asm("fma.rn.f32x2 %0, %1, %2, %0;" : "+l"(d) : "l"(a), "l"(b));
}
__device__ __forceinline__ u64 dup2(float v) {
    union { float2 f; u64 u; } cv; cv.f = make_float2(v, v); return cv.u;
}
__device__ __forceinline__ float2 unpk(u64 v) {
    union { u64 u; float2 f; } cv; cv.u = v; return cv.f;
}

// ---------------- small bookkeeping kernels ----------------
__global__ void init_kernel() {
    if (threadIdx.x < NE) g_counts[threadIdx.x] = 0;
}

__global__ void prefix_kernel() {
    if (threadIdx.x == 0) {
        int s = 0;
        for (int e = 0; e < NE; e++) {
            g_base[e] = s;
            s += g_counts[e];
            g_offsets[e] = 0;
        }
        g_base[NE] = s;
    }
}

__global__ void scatter_kernel() {
    int b = blockIdx.x * blockDim.x + threadIdx.x;
    if (b >= NT) return;
#pragma unroll
    for (int s = 0; s < 2; s++) {
        int e = g_top_i[b * 2 + s];
        int pos = atomicAdd(&g_offsets[e], 1);
        int idx = g_base[e] + pos;
        g_perm_tok[idx] = b;
        g_perm_w[idx] = g_top_w[b * 2 + s];
    }
}

// ---------------- gate layer 3 + softmax + top-2 + renorm ----------------
// one warp per token; 8 tokens per 256-thread block
__global__ void gate3_kernel(const float* __restrict__ h2,
                             const float* __restrict__ g3,
                             const float* __restrict__ gb3,
                             float* __restrict__ y_out,
                             float* __restrict__ p_out) {
    __shared__ float s_g3t[NE][DD];   // transposed: [e][k], conflict-free reads
    int tid = threadIdx.x;
    for (int i = tid; i < DD * NE; i += 256) {
        int k = i >> 4, e = i & 15;
        s_g3t[e][k] = g3[i];
    }
    __syncthreads();

    int warp = tid >> 5, lane = tid & 31;
    int b = blockIdx.x * 8 + warp;

    float acc[NE];
#pragma unroll
    for (int e = 0; e < NE; e++) acc[e] = 0.f;

    const float* hrow = h2 + (size_t)b * DD;
#pragma unroll
    for (int j = 0; j < DD / 32; j++) {
        int k = lane + j * 32;
        float hv = hrow[k];
#pragma unroll
        for (int e = 0; e < NE; e++) acc[e] = fmaf(hv, s_g3t[e][k], acc[e]);
    }
#pragma unroll
    for (int e = 0; e < NE; e++) {
#pragma unroll
        for (int off = 16; off; off >>= 1)
            acc[e] += __shfl_xor_sync(0xffffffffu, acc[e], off);
        acc[e] += gb3[e];    // logits now in every lane
    }

    // softmax + top-2 (computed redundantly in every lane; cheap)
    float m = acc[0];
#pragma unroll
    for (int e = 1; e < NE; e++) m = fmaxf(m, acc[e]);
    float pe[NE];
    float Z = 0.f;
#pragma unroll
    for (int e = 0; e < NE; e++) { pe[e] = expf(acc[e] - m); Z += pe[e]; }
    float invZ = 1.f / Z;

    int i1 = 0; float v1 = pe[0];
#pragma unroll
    for (int e = 1; e < NE; e++) if (pe[e] > v1) { v1 = pe[e]; i1 = e; }
    int i2 = -1; float v2 = -1.f;
#pragma unroll
    for (int e = 0; e < NE; e++) if (e != i1 && pe[e] > v2) { v2 = pe[e]; i2 = e; }

    float t1 = v1 * invZ, t2 = v2 * invZ;
    float denom = t1 + t2 + 1e-9f;
    float w1 = t1 / denom, w2 = t2 / denom;

    // write p row (16 floats)
    if (lane < NE)
        p_out[(size_t)b * NE + lane] = (lane == i1) ? w1 : ((lane == i2) ? w2 : 0.f);
    // zero y row (accumulated later by expert stage 2)
#pragma unroll
    for (int j = 0; j < OO / 32; j++)
        y_out[(size_t)b * OO + lane + j * 32] = 0.f;

    if (lane == 0) {
        g_top_i[b * 2 + 0] = i1;
        g_top_i[b * 2 + 1] = i2;
        g_top_w[b * 2 + 0] = w1;
        g_top_w[b * 2 + 1] = w2;
        atomicAdd(&g_counts[i1], 1);
        atomicAdd(&g_counts[i2], 1);
    }
}

// ---------------- tiled fp32 GEMM (f32x2 packed FMA) ----------------
// MODE 0: C[M,N] = relu(A[M,K] @ W[K,N] + preb[N])              (gate layers 1,2)
// MODE 1: he[slot,N] = relu((x[tok]+ebias[e]) @ W1_e + b1_e)    (expert stage 1, gathered)
// MODE 2: y[tok] += w_slot * ((he[slot] @ W2_e) + b2_e)         (expert stage 2, atomic)
template<int MODE>
__global__ __launch_bounds__(256, 2)
void gemm_tpl(const float* __restrict__ A,
              const float* __restrict__ W,
              const float* __restrict__ preb,
              const float* __restrict__ ebias,
              float* __restrict__ C,
              int N, int K) {
    __shared__ __align__(16) float As[BKK][BM];
    __shared__ __align__(16) float Ws[BKK][BN];
    __shared__ int   s_row[BM];
    __shared__ int   s_tok[BM];
    __shared__ float s_wgt[BM];

    int tid = threadIdx.x;
    int bm = 0, bn;
    int e = 0, rows = BM, tbase = 0;

    if (MODE == 0) {
        bm = blockIdx.x * BM;
        bn = blockIdx.y * BN;
    } else {
        e = blockIdx.z;
        int nbeg = g_base[e];
        int ne = g_base[e + 1] - nbeg;
        int t0 = blockIdx.x * BM;
        if (t0 >= ne) return;
        rows = min(BM, ne - t0);
        tbase = nbeg + t0;
        bn = blockIdx.y * BN;
        for (int mm = tid; mm < BM; mm += 256) {
            int mc = min(mm, rows - 1);
            int slot = tbase + mc;
            if (MODE == 1) {
                s_row[mm] = g_perm_tok[slot];
            } else {
                s_row[mm] = slot;
                s_tok[mm] = g_perm_tok[slot];
                s_wgt[mm] = g_perm_w[slot];
            }
        }
        __syncthreads();
    }

    const float* Wp = (MODE == 0) ? W : (W + (size_t)e * K * N);

    int tr = tid >> 4;   // 0..15 -> rows tr*8 .. tr*8+7
    int tc = tid & 15;   // 0..15 -> cols tc*8 .. tc*8+7

    u64 acc[4][8];
#pragma unroll
    for (int i = 0; i < 4; i++)
#pragma unroll
        for (int j = 0; j < 8; j++) acc[i][j] = 0ull;

    for (int k0 = 0; k0 < K; k0 += BKK) {
        // --- load A tile (transposed into As[k][m]) ---
#pragma unroll
        for (int i = 0; i < 2; i++) {
            int f = tid * 2 + i;          // 0..511
            int m = f >> 2;
            int c = (f & 3) << 2;
            float4 v;
            if (MODE == 0) {
                v = *(const float4*)&A[(size_t)(bm + m) * K + k0 + c];
            } else if (MODE == 1) {
                float4 xv = *(const float4*)&A[(size_t)s_row[m] * K + k0 + c];
                float4 bv = *(const float4*)&ebias[(size_t)e * K + k0 + c];
                v = make_float4(xv.x + bv.x, xv.y + bv.y, xv.z + bv.z, xv.w + bv.w);
            } else {
                v = *(const float4*)&A[(size_t)s_row[m] * K + k0 + c];
            }
            As[c + 0][m] = v.x;
            As[c + 1][m] = v.y;
            As[c + 2][m] = v.z;
            As[c + 3][m] = v.w;
        }
        // --- load W tile ---
#pragma unroll
        for (int i = 0; i < 2; i++) {
            int f = tid * 2 + i;
            int r = f >> 5;               // 0..15
            int c = (f & 31) << 2;        // 0..124
            *(float4*)&Ws[r][c] = *(const float4*)&Wp[(size_t)(k0 + r) * N + bn + c];
        }
        __syncthreads();

        // --- compute: 128x128 tile, rows paired in f32x2 lanes ---
#pragma unroll
        for (int k = 0; k < BKK; k++) {
            u64 a2[4];
            {
                const ulonglong2* ap = (const ulonglong2*)&As[k][tr * 8];
                ulonglong2 p0 = ap[0], p1 = ap[1];
                a2[0] = p0.x; a2[1] = p0.y; a2[2] = p1.x; a2[3] = p1.y;
            }
            float4 wv0 = *(const float4*)&Ws[k][tc * 8];
            float4 wv1 = *(const float4*)&Ws[k][tc * 8 + 4];
            u64 b2r[8] = { dup2(wv0.x), dup2(wv0.y), dup2(wv0.z), dup2(wv0.w),
                           dup2(wv1.x), dup2(wv1.y), dup2(wv1.z), dup2(wv1.w) };
#pragma unroll
            for (int i = 0; i < 4; i++)
#pragma unroll
                for (int j = 0; j < 8; j++)
                    fma2(acc[i][j], a2[i], b2r[j]);
        }
        __syncthreads();
    }

    // --- epilogue ---
    float bv[8];
    {
        const float* pb = preb + ((MODE == 0) ? 0 : (size_t)e * N) + bn + tc * 8;
#pragma unroll
        for (int j = 0; j < 8; j++) bv[j] = pb[j];
    }

#pragma unroll
    for (int i = 0; i < 4; i++) {
        float lo[8], hi[8];
#pragma unroll
        for (int j = 0; j < 8; j++) {
            float2 c2 = unpk(acc[i][j]);
            lo[j] = c2.x + bv[j];
            hi[j] = c2.y + bv[j];
        }
        int m0 = tr * 8 + 2 * i;
        if (MODE == 0) {
            float* cp0 = C + (size_t)(bm + m0) * N + bn + tc * 8;
            float* cp1 = C + (size_t)(bm + m0 + 1) * N + bn + tc * 8;
            *(float4*)cp0       = make_float4(fmaxf(lo[0],0.f), fmaxf(lo[1],0.f), fmaxf(lo[2],0.f), fmaxf(lo[3],0.f));
            *(float4*)(cp0 + 4) = make_float4(fmaxf(lo[4],0.f), fmaxf(lo[5],0.f), fmaxf(lo[6],0.f), fmaxf(lo[7],0.f));
            *(float4*)cp1       = make_float4(fmaxf(hi[0],0.f), fmaxf(hi[1],0.f), fmaxf(hi[2],0.f), fmaxf(hi[3],0.f));
            *(float4*)(cp1 + 4) = make_float4(fmaxf(hi[4],0.f), fmaxf(hi[5],0.f), fmaxf(hi[6],0.f), fmaxf(hi[7],0.f));
        } else if (MODE == 1) {
            if (m0 < rows) {
                float* cp = C + (size_t)(tbase + m0) * N + bn + tc * 8;
                *(float4*)cp       = make_float4(fmaxf(lo[0],0.f), fmaxf(lo[1],0.f), fmaxf(lo[2],0.f), fmaxf(lo[3],0.f));
                *(float4*)(cp + 4) = make_float4(fmaxf(lo[4],0.f), fmaxf(lo[5],0.f), fmaxf(lo[6],0.f), fmaxf(lo[7],0.f));
            }
            if (m0 + 1 < rows) {
                float* cp = C + (size_t)(tbase + m0 + 1) * N + bn + tc * 8;
                *(float4*)cp       = make_float4(fmaxf(hi[0],0.f), fmaxf(hi[1],0.f), fmaxf(hi[2],0.f), fmaxf(hi[3],0.f));
                *(float4*)(cp + 4) = make_float4(fmaxf(hi[4],0.f), fmaxf(hi[5],0.f), fmaxf(hi[6],0.f), fmaxf(hi[7],0.f));
            }
        } else {
            if (m0 < rows) {
                int tok = s_tok[m0]; float w = s_wgt[m0];
                float* yp = C + (size_t)tok * N + bn + tc * 8;
#pragma unroll
                for (int j = 0; j < 8; j++) atomicAdd(&yp[j], lo[j] * w);
            }
            if (m0 + 1 < rows) {
                int tok = s_tok[m0 + 1]; float w = s_wgt[m0 + 1];
                float* yp = C + (size_t)tok * N + bn + tc * 8;
#pragma unroll
                for (int j = 0; j < 8; j++) atomicAdd(&yp[j], hi[j] * w);
            }
        }
    }
}

// ---------------- launch ----------------
extern "C" void kernel_launch(void* const* d_in, const int* in_sizes, int n_in,
                              void* d_out, int out_size) {
    const float* x     = (const float*)d_in[0];
    const float* ebias = (const float*)d_in[1];
    const float* W1    = (const float*)d_in[2];
    const float* b1    = (const float*)d_in[3];
    const float* W2    = (const float*)d_in[4];
    const float* b2    = (const float*)d_in[5];
    const float* g1    = (const float*)d_in[6];
    const float* gb1   = (const float*)d_in[7];
    const float* g2    = (const float*)d_in[8];
    const float* gb2   = (const float*)d_in[9];
    const float* g3    = (const float*)d_in[10];
    const float* gb3   = (const float*)d_in[11];

    float* y = (float*)d_out;                       // [NT, OO]
    float* p = y + (size_t)NT * OO;                 // [NT, NE]

    float *h1p, *h2p, *hep;
    cudaGetSymbolAddress((void**)&h1p, g_h1);
    cudaGetSymbolAddress((void**)&h2p, g_h2);
    cudaGetSymbolAddress((void**)&hep, g_he);

    init_kernel<<<1, 32>>>();

    // gate layer 1: h1 = relu(x @ g1 + gb1)   [65536,256]x[256,1024]
    gemm_tpl<0><<<dim3(NT / BM, GH / BN), 256>>>(x, g1, gb1, nullptr, h1p, GH, DD);
    // gate layer 2: h2 = relu(h1 @ g2 + gb2)  [65536,1024]x[1024,256]
    gemm_tpl<0><<<dim3(NT / BM, DD / BN), 256>>>(h1p, g2, gb2, nullptr, h2p, DD, GH);
    // gate layer 3 + softmax + top2 + renorm; also zeroes y
    gate3_kernel<<<NT / 8, 256>>>(h2p, g3, gb3, y, p);

    prefix_kernel<<<1, 32>>>();
    scatter_kernel<<<NT / 256, 256>>>();

    // expert stage 1: he = relu((x+bias_e) @ W1_e + b1_e), grouped by expert
    gemm_tpl<1><<<dim3(NT * 2 / BM, HH / BN, NE), 256>>>(x, W1, b1, ebias, hep, HH, DD);
    // expert stage 2: y[tok] += w * (he @ W2_e + b2_e)
    gemm_tpl<2><<<dim3(NT * 2 / BM, OO / BN, NE), 256>>>(hep, W2, b2, nullptr, y, OO, HH);
}